// round 15
// baseline (speedup 1.0000x reference)
#include <cuda_runtime.h>
#include <math.h>

#define NN 50000
#define NE 800000
#define HID 128

// ---------- static scratch (allocation-free contract) ----------
// Invariant: g_deg and g_cur are ZERO at entry to kernel_launch.
// (zero-initialized at module load; rowptr2 re-zeroes g_deg, aggx re-zeroes g_cur)
struct __align__(8) CsrEnt { int c; float w; };
__device__ int    g_deg[NN];
__device__ int    g_cur[NN];
__device__ float  g_dis[NN];
__device__ int    g_rowptr[NN + 1];
__device__ CsrEnt g_csr[NE];
__device__ int2   g_se[NE];                 // (src, edge_id) per CSR slot
__device__ int    g_bsum[256];
__device__ float  g_t[(size_t)NN * HID];    // u2 [n,128]
__device__ float  g_h[(size_t)NN * HID];    // h1 [n,128]
__device__ float  g_ab[(size_t)NN * 256];   // [A | B] per node
__device__ float  g_w2ab[128 * 256];        // W2 @ [W_A | W_B]
__device__ float  g_bab[256];               // b2 @ [W_A | W_B]

// ---------- f32x2 packed FMA (PTX-only; exact fp32 semantics) ----------
__device__ __forceinline__ unsigned long long ffma2(unsigned long long a,
                                                    unsigned long long b,
                                                    unsigned long long c) {
    unsigned long long d;
    asm("fma.rn.f32x2 %0, %1, %2, %3;" : "=l"(d) : "l"(a), "l"(b), "l"(c));
    return d;
}

// ---------- graph build ----------
// 1 edge per thread: scatter/atomic phases want max thread parallelism (measured)
__global__ void indeg_kernel(const int* __restrict__ ei, int E) {
    int e = blockIdx.x * blockDim.x + threadIdx.x;
    if (e < E) atomicAdd(&g_deg[ei[E + e]], 1);
}

// dis + per-block degree sums (fused)
__global__ void disbsum_kernel(int n) {
    __shared__ int sm[8];
    int b = blockIdx.x;
    int i = b * 256 + threadIdx.x;
    int v = (i < n) ? g_deg[i] : 0;
    if (i < n) g_dis[i] = rsqrtf((float)(v + 1));
    int lane = threadIdx.x & 31, wid = threadIdx.x >> 5;
    int s = v;
    #pragma unroll
    for (int off = 16; off; off >>= 1) s += __shfl_xor_sync(0xffffffffu, s, off);
    if (lane == 0) sm[wid] = s;
    __syncthreads();
    if (wid == 0) {
        int t = (lane < 8) ? sm[lane] : 0;
        #pragma unroll
        for (int off = 4; off; off >>= 1) t += __shfl_xor_sync(0xffffffffu, t, off);
        if (lane == 0) g_bsum[b] = t;
    }
}

// rowptr: every block reduces the (<=256) block-sums itself, then local scan.
// Also re-zeroes g_deg (only block b reads g_deg[b*256..], so safe).
__global__ void rowptr2_kernel(int nb, int n) {
    __shared__ unsigned long long psm[8];
    __shared__ int wsum[8];
    __shared__ int s_boff, s_tot;
    int b = blockIdx.x, tid = threadIdx.x;
    int lane = tid & 31, wid = tid >> 5;

    unsigned long long pv = 0ull;
    if (tid < nb) {
        unsigned long long xv = (unsigned int)g_bsum[tid];
        pv = (xv << 32) | ((tid < b) ? xv : 0ull);
    }
    #pragma unroll
    for (int off = 16; off; off >>= 1) pv += __shfl_xor_sync(0xffffffffu, pv, off);
    if (lane == 0) psm[wid] = pv;
    __syncthreads();
    if (wid == 0) {
        unsigned long long t = (lane < 8) ? psm[lane] : 0ull;
        #pragma unroll
        for (int off = 4; off; off >>= 1) t += __shfl_xor_sync(0xffffffffu, t, off);
        if (lane == 0) { s_boff = (int)(t & 0xffffffffull); s_tot = (int)(t >> 32); }
    }
    __syncthreads();

    int i = b * 256 + tid;
    int v = (i < n) ? g_deg[i] : 0;
    int s = v;
    #pragma unroll
    for (int off = 1; off < 32; off <<= 1) {
        int t = __shfl_up_sync(0xffffffffu, s, off);
        if (lane >= off) s += t;
    }
    if (lane == 31) wsum[wid] = s;
    __syncthreads();
    if (wid == 0 && lane < 8) {
        int ws = wsum[lane];
        #pragma unroll
        for (int off = 1; off < 8; off <<= 1) {
            int t = __shfl_up_sync(0xffu, ws, off);
            if (lane >= off) ws += t;
        }
        wsum[lane] = ws;
    }
    __syncthreads();
    int excl = s - v + ((wid > 0) ? wsum[wid - 1] : 0);
    if (i < n) { g_rowptr[i] = s_boff + excl; g_deg[i] = 0; }
    if (b == gridDim.x - 1 && tid == 0) g_rowptr[n] = s_tot;
}

// 1 edge per thread: maximum chip-wide atomic parallelism (measured best)
__global__ void fill_kernel(const int* __restrict__ ei, int E) {
    int e = blockIdx.x * blockDim.x + threadIdx.x;
    if (e >= E) return;
    int s = ei[e];
    int c = ei[E + e];
    int pos = g_rowptr[c] + atomicAdd(&g_cur[c], 1);
    CsrEnt en; en.c = s; en.w = g_dis[s] * g_dis[c];
    g_csr[pos] = en;
    g_se[pos] = make_int2(s, e);
}

// ---------- fused layer 1: u1 = agg(x) (5-dim), h1 = relu(u1@W1 + b1) ----------
// 8 lanes per edge. Also re-zeroes g_cur (self-cleaning invariant).
__global__ void aggx_gemm1_kernel(const float* __restrict__ x, const float* __restrict__ W1,
                                  const float* __restrict__ b1, int n) {
    __shared__ float Ws[5][HID];
    __shared__ float bs[HID];
    int tid = threadIdx.x;   // 256
    if (tid < HID) {
        #pragma unroll
        for (int f = 0; f < 5; f++) Ws[f][tid] = W1[f * HID + tid];
        bs[tid] = b1[tid];
    }
    __syncthreads();
    int gwid = (blockIdx.x * blockDim.x + tid) >> 5;
    int lane = tid & 31;
    if (gwid >= n) return;
    int node = gwid;
    int beg = g_rowptr[node], end = g_rowptr[node + 1];
    if (lane == 0) g_cur[node] = 0;      // restore invariant for next replay
    int grp = lane >> 3, sub = lane & 7;
    float d = g_dis[node];
    float acc = 0.f;
    if (grp == 0 && sub < 5)
        acc = d * d * __ldg(&x[(size_t)node * 5 + sub]);   // self-loop term
    for (int e = beg + grp; e < end; e += 4) {
        unsigned long long raw = __ldg((const unsigned long long*)&g_csr[e]);
        int   src = (int)(raw & 0xffffffffull);
        float w   = __int_as_float((unsigned int)(raw >> 32));
        float v = (sub < 5) ? __ldg(&x[(size_t)src * 5 + sub]) : 0.f;
        acc += w * v;
    }
    acc += __shfl_xor_sync(0xffffffffu, acc, 8);
    acc += __shfl_xor_sync(0xffffffffu, acc, 16);
    float u0 = __shfl_sync(0xffffffffu, acc, 0);
    float u1 = __shfl_sync(0xffffffffu, acc, 1);
    float u2 = __shfl_sync(0xffffffffu, acc, 2);
    float u3 = __shfl_sync(0xffffffffu, acc, 3);
    float u4 = __shfl_sync(0xffffffffu, acc, 4);
    float4 h;
    int c = lane * 4;
    h.x = fmaxf(bs[c+0] + u0*Ws[0][c+0] + u1*Ws[1][c+0] + u2*Ws[2][c+0] + u3*Ws[3][c+0] + u4*Ws[4][c+0], 0.f);
    h.y = fmaxf(bs[c+1] + u0*Ws[0][c+1] + u1*Ws[1][c+1] + u2*Ws[2][c+1] + u3*Ws[3][c+1] + u4*Ws[4][c+1], 0.f);
    h.z = fmaxf(bs[c+2] + u0*Ws[0][c+2] + u1*Ws[1][c+2] + u2*Ws[2][c+2] + u3*Ws[3][c+2] + u4*Ws[4][c+2], 0.f);
    h.w = fmaxf(bs[c+3] + u0*Ws[0][c+3] + u1*Ws[1][c+3] + u2*Ws[2][c+3] + u3*Ws[3][c+3] + u4*Ws[4][c+3], 0.f);
    *((float4*)(g_h + (size_t)node * HID) + lane) = h;
}

// ---------- layer-2 aggregation: u2 = agg(h1), unroll 4 ----------
__global__ void agg2_kernel(int n) {
    int gwid = (blockIdx.x * blockDim.x + threadIdx.x) >> 5;
    int lane = threadIdx.x & 31;
    if (gwid >= n) return;
    int node = gwid;
    float d = g_dis[node];
    float self = d * d;
    float4 hv = *((const float4*)(g_h + (size_t)node * HID) + lane);
    float4 acc = make_float4(self * hv.x, self * hv.y, self * hv.z, self * hv.w);
    int beg = g_rowptr[node], end = g_rowptr[node + 1];
    int e = beg;
    for (; e + 3 < end; e += 4) {
        unsigned long long r0 = __ldg((const unsigned long long*)&g_csr[e]);
        unsigned long long r1 = __ldg((const unsigned long long*)&g_csr[e + 1]);
        unsigned long long r2 = __ldg((const unsigned long long*)&g_csr[e + 2]);
        unsigned long long r3 = __ldg((const unsigned long long*)&g_csr[e + 3]);
        CsrEnt e0 = *(CsrEnt*)&r0;
        CsrEnt e1 = *(CsrEnt*)&r1;
        CsrEnt e2 = *(CsrEnt*)&r2;
        CsrEnt e3 = *(CsrEnt*)&r3;
        float4 v0 = __ldg((const float4*)(g_h + (size_t)e0.c * HID) + lane);
        float4 v1 = __ldg((const float4*)(g_h + (size_t)e1.c * HID) + lane);
        float4 v2 = __ldg((const float4*)(g_h + (size_t)e2.c * HID) + lane);
        float4 v3 = __ldg((const float4*)(g_h + (size_t)e3.c * HID) + lane);
        acc.x += e0.w * v0.x; acc.y += e0.w * v0.y; acc.z += e0.w * v0.z; acc.w += e0.w * v0.w;
        acc.x += e1.w * v1.x; acc.y += e1.w * v1.y; acc.z += e1.w * v1.z; acc.w += e1.w * v1.w;
        acc.x += e2.w * v2.x; acc.y += e2.w * v2.y; acc.z += e2.w * v2.z; acc.w += e2.w * v2.w;
        acc.x += e3.w * v3.x; acc.y += e3.w * v3.y; acc.z += e3.w * v3.z; acc.w += e3.w * v3.w;
    }
    for (; e < end; e++) {
        unsigned long long r0 = __ldg((const unsigned long long*)&g_csr[e]);
        CsrEnt e0 = *(CsrEnt*)&r0;
        float4 v0 = __ldg((const float4*)(g_h + (size_t)e0.c * HID) + lane);
        acc.x += e0.w * v0.x; acc.y += e0.w * v0.y; acc.z += e0.w * v0.z; acc.w += e0.w * v0.w;
    }
    *((float4*)(g_t + (size_t)node * HID) + lane) = acc;
}

// ---------- combined weights: W2AB = W2 @ [W_A|W_B]; block 128 does bias ----------
__global__ void wcomb_kernel(const float* __restrict__ W2, const float* __restrict__ b2,
                             const float* __restrict__ Wm1) {
    __shared__ float w2row[128];
    int k = blockIdx.x;       // 0..127 = rows, 128 = bias
    int j = threadIdx.x;      // 0..255 output col
    if (j < 128) w2row[j] = (k < 128) ? W2[k * 128 + j] : b2[j];
    __syncthreads();
    const float* base = (j < 128) ? (Wm1 + j) : (Wm1 + 128 * 128 + (j - 128));
    float acc = 0.f;
    #pragma unroll 8
    for (int q = 0; q < 128; q++) acc += w2row[q] * base[(size_t)q * 128];
    if (k < 128) g_w2ab[k * 256 + j] = acc;
    else         g_bab[j] = acc;
}

// ---------- [A|B] = u2 @ W2AB + bAB : [n,128] @ [128,256] (packed f32x2) ----------
__global__ void gemm256_kernel(const float* __restrict__ H, const float* __restrict__ W,
                               const float* __restrict__ bias, float* __restrict__ O, int n) {
    __shared__ float4 Wsa[16][32];
    __shared__ float4 Wsb[16][32];
    __shared__ float2 Hs2[16][66];
    int tid = threadIdx.x;
    int c8  = tid & 31;
    int r0  = (tid >> 5) * 8;
    int row0 = blockIdx.x * 64;

    unsigned long long acc[8][4];
    #pragma unroll
    for (int r = 0; r < 8; r++)
        #pragma unroll
        for (int j = 0; j < 4; j++) acc[r][j] = 0ull;

    for (int k0 = 0; k0 < HID; k0 += 16) {
        #pragma unroll
        for (int i = 0; i < 4; i++) {
            int q = tid + i * 256;
            int kk = q >> 6, cc = q & 63;
            float4 v = *(const float4*)&W[(size_t)(k0 + kk) * 256 + cc * 4];
            if (cc & 1) Wsb[kk][cc >> 1] = v; else Wsa[kk][cc >> 1] = v;
        }
        {
            int q = tid;
            int r = q >> 2, kq = (q & 3) * 4;
            int gr = row0 + r;
            float4 hv = make_float4(0.f, 0.f, 0.f, 0.f);
            if (gr < n) hv = *(const float4*)&H[(size_t)gr * HID + k0 + kq];
            Hs2[kq + 0][r] = make_float2(hv.x, hv.x);
            Hs2[kq + 1][r] = make_float2(hv.y, hv.y);
            Hs2[kq + 2][r] = make_float2(hv.z, hv.z);
            Hs2[kq + 3][r] = make_float2(hv.w, hv.w);
        }
        __syncthreads();
        #pragma unroll
        for (int kk = 0; kk < 16; kk++) {
            ulonglong2 wa = *(ulonglong2*)&Wsa[kk][c8];
            ulonglong2 wb = *(ulonglong2*)&Wsb[kk][c8];
            #pragma unroll
            for (int r = 0; r < 8; r++) {
                unsigned long long h2 = *(unsigned long long*)&Hs2[kk][r0 + r];
                acc[r][0] = ffma2(h2, wa.x, acc[r][0]);
                acc[r][1] = ffma2(h2, wa.y, acc[r][1]);
                acc[r][2] = ffma2(h2, wb.x, acc[r][2]);
                acc[r][3] = ffma2(h2, wb.y, acc[r][3]);
            }
        }
        __syncthreads();
    }
    float4 bv0 = *(const float4*)&bias[c8 * 8];
    float4 bv1 = *(const float4*)&bias[c8 * 8 + 4];
    #pragma unroll
    for (int r = 0; r < 8; r++) {
        int gr = row0 + r0 + r;
        if (gr < n) {
            float2 p0 = *(float2*)&acc[r][0];
            float2 p1 = *(float2*)&acc[r][1];
            float2 p2 = *(float2*)&acc[r][2];
            float2 p3 = *(float2*)&acc[r][3];
            float4 o0 = make_float4(p0.x + bv0.x, p0.y + bv0.y, p1.x + bv0.z, p1.y + bv0.w);
            float4 o1 = make_float4(p2.x + bv1.x, p2.y + bv1.y, p3.x + bv1.z, p3.y + bv1.w);
            *(float4*)&O[(size_t)gr * 256 + c8 * 8]     = o0;
            *(float4*)&O[(size_t)gr * 256 + c8 * 8 + 4] = o1;
        }
    }
}

// ---------- per-edge MLP head, grouped by dst, unroll 4 ----------
__device__ __forceinline__ float edge_dot(float4 A, float4 Bb, float4 ev,
                                          float4 w0, float4 w1, float4 w2, float4 w3,
                                          float4 v2) {
    float4 z;
    z.x = A.x + Bb.x + ev.x*w0.x + ev.y*w1.x + ev.z*w2.x + ev.w*w3.x;
    z.y = A.y + Bb.y + ev.x*w0.y + ev.y*w1.y + ev.z*w2.y + ev.w*w3.y;
    z.z = A.z + Bb.z + ev.x*w0.z + ev.y*w1.z + ev.z*w2.z + ev.w*w3.z;
    z.w = A.w + Bb.w + ev.x*w0.w + ev.y*w1.w + ev.z*w2.w + ev.w*w3.w;
    return fmaxf(z.x,0.f)*v2.x + fmaxf(z.y,0.f)*v2.y + fmaxf(z.z,0.f)*v2.z + fmaxf(z.w,0.f)*v2.w;
}

__global__ void edge_kernel(const float* __restrict__ ea,
                            const float* __restrict__ WmE,
                            const float* __restrict__ bm1, const float* __restrict__ Wm2,
                            const float* __restrict__ bm2, float* __restrict__ out, int n) {
    __shared__ float4 sWe[4][32];
    __shared__ float4 sb4[32];
    __shared__ float4 sw24[32];
    __shared__ float sbm2;
    int tid = threadIdx.x;  // 256
    if (tid < 128) sWe[tid >> 5][tid & 31] = *(const float4*)&WmE[(tid >> 5) * HID + (tid & 31) * 4];
    else if (tid < 160) sb4[tid - 128] = *(const float4*)&bm1[(tid - 128) * 4];
    else if (tid < 192) sw24[tid - 160] = *(const float4*)&Wm2[(tid - 160) * 4];
    else if (tid == 192) sbm2 = bm2[0];
    __syncthreads();
    int gwid = (blockIdx.x * blockDim.x + tid) >> 5;
    int lane = tid & 31;
    if (gwid >= n) return;
    int node = gwid;
    int beg = g_rowptr[node], end = g_rowptr[node + 1];
    if (beg == end) return;
    float4 Bb = *(const float4*)&g_ab[(size_t)node * 256 + HID + lane * 4];
    float4 bi = sb4[lane];
    Bb.x += bi.x; Bb.y += bi.y; Bb.z += bi.z; Bb.w += bi.w;
    float4 w0 = sWe[0][lane], w1 = sWe[1][lane], w2 = sWe[2][lane], w3 = sWe[3][lane];
    float4 v2 = sw24[lane];
    float bm2v = sbm2;
    int e = beg;
    for (; e + 3 < end; e += 4) {
        int2 se0 = __ldg(&g_se[e]);
        int2 se1 = __ldg(&g_se[e + 1]);
        int2 se2 = __ldg(&g_se[e + 2]);
        int2 se3 = __ldg(&g_se[e + 3]);
        float4 A0 = __ldg((const float4*)(g_ab + (size_t)se0.x * 256) + lane);
        float4 A1 = __ldg((const float4*)(g_ab + (size_t)se1.x * 256) + lane);
        float4 A2 = __ldg((const float4*)(g_ab + (size_t)se2.x * 256) + lane);
        float4 A3 = __ldg((const float4*)(g_ab + (size_t)se3.x * 256) + lane);
        float4 ev0 = __ldg((const float4*)&ea[(size_t)se0.y * 4]);
        float4 ev1 = __ldg((const float4*)&ea[(size_t)se1.y * 4]);
        float4 ev2 = __ldg((const float4*)&ea[(size_t)se2.y * 4]);
        float4 ev3 = __ldg((const float4*)&ea[(size_t)se3.y * 4]);
        float p0 = edge_dot(A0, Bb, ev0, w0, w1, w2, w3, v2);
        float p1 = edge_dot(A1, Bb, ev1, w0, w1, w2, w3, v2);
        float p2 = edge_dot(A2, Bb, ev2, w0, w1, w2, w3, v2);
        float p3 = edge_dot(A3, Bb, ev3, w0, w1, w2, w3, v2);
        #pragma unroll
        for (int off = 16; off; off >>= 1) {
            p0 += __shfl_xor_sync(0xffffffffu, p0, off);
            p1 += __shfl_xor_sync(0xffffffffu, p1, off);
            p2 += __shfl_xor_sync(0xffffffffu, p2, off);
            p3 += __shfl_xor_sync(0xffffffffu, p3, off);
        }
        if (lane == 0) out[se0.y] = 1.f / (1.f + __expf(-(p0 + bm2v)));
        if (lane == 1) out[se1.y] = 1.f / (1.f + __expf(-(p1 + bm2v)));
        if (lane == 2) out[se2.y] = 1.f / (1.f + __expf(-(p2 + bm2v)));
        if (lane == 3) out[se3.y] = 1.f / (1.f + __expf(-(p3 + bm2v)));
    }
    for (; e < end; e++) {
        int2 se0 = __ldg(&g_se[e]);
        float4 A0 = __ldg((const float4*)(g_ab + (size_t)se0.x * 256) + lane);
        float4 ev0 = __ldg((const float4*)&ea[(size_t)se0.y * 4]);
        float p0 = edge_dot(A0, Bb, ev0, w0, w1, w2, w3, v2);
        #pragma unroll
        for (int off = 16; off; off >>= 1)
            p0 += __shfl_xor_sync(0xffffffffu, p0, off);
        if (lane == 0) out[se0.y] = 1.f / (1.f + __expf(-(p0 + bm2v)));
    }
}

// ---------- launcher ----------
extern "C" void kernel_launch(void* const* d_in, const int* in_sizes, int n_in,
                              void* d_out, int out_size) {
    const float* x    = (const float*)d_in[0];
    const float* ea   = (const float*)d_in[1];
    const float* W1   = (const float*)d_in[2];
    const float* b1   = (const float*)d_in[3];
    const float* W2   = (const float*)d_in[4];
    const float* b2   = (const float*)d_in[5];
    const float* Wm1  = (const float*)d_in[6];
    const float* bm1  = (const float*)d_in[7];
    const float* Wm2  = (const float*)d_in[8];
    const float* bm2  = (const float*)d_in[9];
    const int*   ei   = (const int*)d_in[10];   // int32 (JAX x64 disabled)
    float* out = (float*)d_out;

    int n = in_sizes[0] / 5;          // 50000
    int E = in_sizes[10] / 2;         // 800000
    int nb = (n + 255) / 256;

    float *p_t, *p_ab, *p_w2ab, *p_bab;
    cudaGetSymbolAddress((void**)&p_t, g_t);
    cudaGetSymbolAddress((void**)&p_ab, g_ab);
    cudaGetSymbolAddress((void**)&p_w2ab, g_w2ab);
    cudaGetSymbolAddress((void**)&p_bab, g_bab);

    // one-time resources (handles cached; per-call work identical & deterministic)
    static cudaStream_t s2 = nullptr;
    static cudaEvent_t evFork = nullptr, evJoin = nullptr;
    if (!s2) {
        cudaStreamCreateWithFlags(&s2, cudaStreamNonBlocking);
        cudaEventCreateWithFlags(&evFork, cudaEventDisableTiming);
        cudaEventCreateWithFlags(&evJoin, cudaEventDisableTiming);
    }

    // fork: wcomb (independent until gemm256) runs concurrently on s2
    cudaEventRecord(evFork, 0);
    cudaStreamWaitEvent(s2, evFork, 0);
    wcomb_kernel<<<129, 256, 0, s2>>>(W2, b2, Wm1);
    cudaEventRecord(evJoin, s2);

    // graph build — no memsets: g_deg/g_cur zeroed by prior invocation (or load)
    indeg_kernel<<<(E + 255) / 256, 256>>>(ei, E);
    disbsum_kernel<<<nb, 256>>>(n);
    rowptr2_kernel<<<nb, 256>>>(nb, n);                      // re-zeroes g_deg
    fill_kernel<<<(E + 255) / 256, 256>>>(ei, E);

    // layer 1 fused: h1 = relu(agg(x) @ W1 + b1)  (re-zeroes g_cur)
    aggx_gemm1_kernel<<<(n * 32 + 255) / 256, 256>>>(x, W1, b1, n);

    // layer 2 aggregation
    agg2_kernel<<<(n * 32 + 255) / 256, 256>>>(n);

    // join wcomb, then projection GEMM
    cudaStreamWaitEvent(0, evJoin, 0);
    gemm256_kernel<<<(n + 63) / 64, 256>>>(p_t, p_w2ab, p_bab, p_ab, n);

    // per-edge head grouped by dst
    edge_kernel<<<(n * 32 + 255) / 256, 256>>>(ea, Wm1 + 256 * HID, bm1, Wm2, bm2, out, n);
}

// round 16
// speedup vs baseline: 1.0255x; 1.0255x over previous
#include <cuda_runtime.h>
#include <math.h>

#define NN 50000
#define NE 800000
#define HID 128

// ---------- static scratch (allocation-free contract) ----------
// Invariant: g_deg and g_cur are ZERO at entry to kernel_launch.
// (zero-initialized at module load; rowptr2 re-zeroes g_deg, aggx re-zeroes g_cur)
struct __align__(8) CsrEnt { int c; float w; };
__device__ int    g_deg[NN];
__device__ int    g_cur[NN];
__device__ float  g_dis[NN];
__device__ int    g_rowptr[NN + 1];
__device__ CsrEnt g_csr[NE];
__device__ int2   g_se[NE];                 // (src, edge_id) per CSR slot
__device__ int    g_bsum[256];
__device__ float  g_t[(size_t)NN * HID];    // u2 [n,128]
__device__ float  g_h[(size_t)NN * HID];    // h1 [n,128]
__device__ float  g_ab[(size_t)NN * 256];   // [A | B] per node
__device__ float  g_w2ab[128 * 256];        // W2 @ [W_A | W_B]
__device__ float  g_bab[256];               // b2 @ [W_A | W_B]

// ---------- f32x2 packed FMA (PTX-only; exact fp32 semantics) ----------
__device__ __forceinline__ unsigned long long ffma2(unsigned long long a,
                                                    unsigned long long b,
                                                    unsigned long long c) {
    unsigned long long d;
    asm("fma.rn.f32x2 %0, %1, %2, %3;" : "=l"(d) : "l"(a), "l"(b), "l"(c));
    return d;
}

// ---------- graph build ----------
// indeg: atomic-without-dependent-work -> throughput-bound; 4 edges/thread + int4
// index loads minimize instruction traffic (measured best in round 14).
__global__ void indeg_kernel(const int* __restrict__ ei, int E) {
    int q = blockIdx.x * blockDim.x + threadIdx.x;
    int base = q * 4;
    if (base + 3 < E) {
        int4 d4 = *(const int4*)&ei[E + base];
        atomicAdd(&g_deg[d4.x], 1);
        atomicAdd(&g_deg[d4.y], 1);
        atomicAdd(&g_deg[d4.z], 1);
        atomicAdd(&g_deg[d4.w], 1);
    } else {
        for (int e = base; e < E; e++) atomicAdd(&g_deg[ei[E + e]], 1);
    }
}

// dis + per-block degree sums (fused)
__global__ void disbsum_kernel(int n) {
    __shared__ int sm[8];
    int b = blockIdx.x;
    int i = b * 256 + threadIdx.x;
    int v = (i < n) ? g_deg[i] : 0;
    if (i < n) g_dis[i] = rsqrtf((float)(v + 1));
    int lane = threadIdx.x & 31, wid = threadIdx.x >> 5;
    int s = v;
    #pragma unroll
    for (int off = 16; off; off >>= 1) s += __shfl_xor_sync(0xffffffffu, s, off);
    if (lane == 0) sm[wid] = s;
    __syncthreads();
    if (wid == 0) {
        int t = (lane < 8) ? sm[lane] : 0;
        #pragma unroll
        for (int off = 4; off; off >>= 1) t += __shfl_xor_sync(0xffffffffu, t, off);
        if (lane == 0) g_bsum[b] = t;
    }
}

// rowptr: every block reduces the (<=256) block-sums itself, then local scan.
// Also re-zeroes g_deg (only block b reads g_deg[b*256..], so safe).
__global__ void rowptr2_kernel(int nb, int n) {
    __shared__ unsigned long long psm[8];
    __shared__ int wsum[8];
    __shared__ int s_boff, s_tot;
    int b = blockIdx.x, tid = threadIdx.x;
    int lane = tid & 31, wid = tid >> 5;

    unsigned long long pv = 0ull;
    if (tid < nb) {
        unsigned long long xv = (unsigned int)g_bsum[tid];
        pv = (xv << 32) | ((tid < b) ? xv : 0ull);
    }
    #pragma unroll
    for (int off = 16; off; off >>= 1) pv += __shfl_xor_sync(0xffffffffu, pv, off);
    if (lane == 0) psm[wid] = pv;
    __syncthreads();
    if (wid == 0) {
        unsigned long long t = (lane < 8) ? psm[lane] : 0ull;
        #pragma unroll
        for (int off = 4; off; off >>= 1) t += __shfl_xor_sync(0xffffffffu, t, off);
        if (lane == 0) { s_boff = (int)(t & 0xffffffffull); s_tot = (int)(t >> 32); }
    }
    __syncthreads();

    int i = b * 256 + tid;
    int v = (i < n) ? g_deg[i] : 0;
    int s = v;
    #pragma unroll
    for (int off = 1; off < 32; off <<= 1) {
        int t = __shfl_up_sync(0xffffffffu, s, off);
        if (lane >= off) s += t;
    }
    if (lane == 31) wsum[wid] = s;
    __syncthreads();
    if (wid == 0 && lane < 8) {
        int ws = wsum[lane];
        #pragma unroll
        for (int off = 1; off < 8; off <<= 1) {
            int t = __shfl_up_sync(0xffu, ws, off);
            if (lane >= off) ws += t;
        }
        wsum[lane] = ws;
    }
    __syncthreads();
    int excl = s - v + ((wid > 0) ? wsum[wid - 1] : 0);
    if (i < n) { g_rowptr[i] = s_boff + excl; g_deg[i] = 0; }
    if (b == gridDim.x - 1 && tid == 0) g_rowptr[n] = s_tot;
}

// fill: atomic-with-return feeding dependent scatter stores -> latency-bound;
// 1 edge per thread maximizes chip-wide outstanding chains (measured best).
__global__ void fill_kernel(const int* __restrict__ ei, int E) {
    int e = blockIdx.x * blockDim.x + threadIdx.x;
    if (e >= E) return;
    int s = ei[e];
    int c = ei[E + e];
    int pos = g_rowptr[c] + atomicAdd(&g_cur[c], 1);
    CsrEnt en; en.c = s; en.w = g_dis[s] * g_dis[c];
    g_csr[pos] = en;
    g_se[pos] = make_int2(s, e);
}

// ---------- fused layer 1: u1 = agg(x) (5-dim), h1 = relu(u1@W1 + b1) ----------
// 8 lanes per edge. Also re-zeroes g_cur (self-cleaning invariant).
__global__ void aggx_gemm1_kernel(const float* __restrict__ x, const float* __restrict__ W1,
                                  const float* __restrict__ b1, int n) {
    __shared__ float Ws[5][HID];
    __shared__ float bs[HID];
    int tid = threadIdx.x;   // 256
    if (tid < HID) {
        #pragma unroll
        for (int f = 0; f < 5; f++) Ws[f][tid] = W1[f * HID + tid];
        bs[tid] = b1[tid];
    }
    __syncthreads();
    int gwid = (blockIdx.x * blockDim.x + tid) >> 5;
    int lane = tid & 31;
    if (gwid >= n) return;
    int node = gwid;
    int beg = g_rowptr[node], end = g_rowptr[node + 1];
    if (lane == 0) g_cur[node] = 0;      // restore invariant for next replay
    int grp = lane >> 3, sub = lane & 7;
    float d = g_dis[node];
    float acc = 0.f;
    if (grp == 0 && sub < 5)
        acc = d * d * __ldg(&x[(size_t)node * 5 + sub]);   // self-loop term
    for (int e = beg + grp; e < end; e += 4) {
        unsigned long long raw = __ldg((const unsigned long long*)&g_csr[e]);
        int   src = (int)(raw & 0xffffffffull);
        float w   = __int_as_float((unsigned int)(raw >> 32));
        float v = (sub < 5) ? __ldg(&x[(size_t)src * 5 + sub]) : 0.f;
        acc += w * v;
    }
    acc += __shfl_xor_sync(0xffffffffu, acc, 8);
    acc += __shfl_xor_sync(0xffffffffu, acc, 16);
    float u0 = __shfl_sync(0xffffffffu, acc, 0);
    float u1 = __shfl_sync(0xffffffffu, acc, 1);
    float u2 = __shfl_sync(0xffffffffu, acc, 2);
    float u3 = __shfl_sync(0xffffffffu, acc, 3);
    float u4 = __shfl_sync(0xffffffffu, acc, 4);
    float4 h;
    int c = lane * 4;
    h.x = fmaxf(bs[c+0] + u0*Ws[0][c+0] + u1*Ws[1][c+0] + u2*Ws[2][c+0] + u3*Ws[3][c+0] + u4*Ws[4][c+0], 0.f);
    h.y = fmaxf(bs[c+1] + u0*Ws[0][c+1] + u1*Ws[1][c+1] + u2*Ws[2][c+1] + u3*Ws[3][c+1] + u4*Ws[4][c+1], 0.f);
    h.z = fmaxf(bs[c+2] + u0*Ws[0][c+2] + u1*Ws[1][c+2] + u2*Ws[2][c+2] + u3*Ws[3][c+2] + u4*Ws[4][c+2], 0.f);
    h.w = fmaxf(bs[c+3] + u0*Ws[0][c+3] + u1*Ws[1][c+3] + u2*Ws[2][c+3] + u3*Ws[3][c+3] + u4*Ws[4][c+3], 0.f);
    *((float4*)(g_h + (size_t)node * HID) + lane) = h;
}

// ---------- layer-2 aggregation: u2 = agg(h1), unroll 4 ----------
__global__ void agg2_kernel(int n) {
    int gwid = (blockIdx.x * blockDim.x + threadIdx.x) >> 5;
    int lane = threadIdx.x & 31;
    if (gwid >= n) return;
    int node = gwid;
    float d = g_dis[node];
    float self = d * d;
    float4 hv = *((const float4*)(g_h + (size_t)node * HID) + lane);
    float4 acc = make_float4(self * hv.x, self * hv.y, self * hv.z, self * hv.w);
    int beg = g_rowptr[node], end = g_rowptr[node + 1];
    int e = beg;
    for (; e + 3 < end; e += 4) {
        unsigned long long r0 = __ldg((const unsigned long long*)&g_csr[e]);
        unsigned long long r1 = __ldg((const unsigned long long*)&g_csr[e + 1]);
        unsigned long long r2 = __ldg((const unsigned long long*)&g_csr[e + 2]);
        unsigned long long r3 = __ldg((const unsigned long long*)&g_csr[e + 3]);
        CsrEnt e0 = *(CsrEnt*)&r0;
        CsrEnt e1 = *(CsrEnt*)&r1;
        CsrEnt e2 = *(CsrEnt*)&r2;
        CsrEnt e3 = *(CsrEnt*)&r3;
        float4 v0 = __ldg((const float4*)(g_h + (size_t)e0.c * HID) + lane);
        float4 v1 = __ldg((const float4*)(g_h + (size_t)e1.c * HID) + lane);
        float4 v2 = __ldg((const float4*)(g_h + (size_t)e2.c * HID) + lane);
        float4 v3 = __ldg((const float4*)(g_h + (size_t)e3.c * HID) + lane);
        acc.x += e0.w * v0.x; acc.y += e0.w * v0.y; acc.z += e0.w * v0.z; acc.w += e0.w * v0.w;
        acc.x += e1.w * v1.x; acc.y += e1.w * v1.y; acc.z += e1.w * v1.z; acc.w += e1.w * v1.w;
        acc.x += e2.w * v2.x; acc.y += e2.w * v2.y; acc.z += e2.w * v2.z; acc.w += e2.w * v2.w;
        acc.x += e3.w * v3.x; acc.y += e3.w * v3.y; acc.z += e3.w * v3.z; acc.w += e3.w * v3.w;
    }
    for (; e < end; e++) {
        unsigned long long r0 = __ldg((const unsigned long long*)&g_csr[e]);
        CsrEnt e0 = *(CsrEnt*)&r0;
        float4 v0 = __ldg((const float4*)(g_h + (size_t)e0.c * HID) + lane);
        acc.x += e0.w * v0.x; acc.y += e0.w * v0.y; acc.z += e0.w * v0.z; acc.w += e0.w * v0.w;
    }
    *((float4*)(g_t + (size_t)node * HID) + lane) = acc;
}

// ---------- combined weights: W2AB = W2 @ [W_A|W_B]; block 128 does bias ----------
__global__ void wcomb_kernel(const float* __restrict__ W2, const float* __restrict__ b2,
                             const float* __restrict__ Wm1) {
    __shared__ float w2row[128];
    int k = blockIdx.x;       // 0..127 = rows, 128 = bias
    int j = threadIdx.x;      // 0..255 output col
    if (j < 128) w2row[j] = (k < 128) ? W2[k * 128 + j] : b2[j];
    __syncthreads();
    const float* base = (j < 128) ? (Wm1 + j) : (Wm1 + 128 * 128 + (j - 128));
    float acc = 0.f;
    #pragma unroll 8
    for (int q = 0; q < 128; q++) acc += w2row[q] * base[(size_t)q * 128];
    if (k < 128) g_w2ab[k * 256 + j] = acc;
    else         g_bab[j] = acc;
}

// ---------- [A|B] = u2 @ W2AB + bAB : [n,128] @ [128,256] (packed f32x2) ----------
__global__ void gemm256_kernel(const float* __restrict__ H, const float* __restrict__ W,
                               const float* __restrict__ bias, float* __restrict__ O, int n) {
    __shared__ float4 Wsa[16][32];
    __shared__ float4 Wsb[16][32];
    __shared__ float2 Hs2[16][66];
    int tid = threadIdx.x;
    int c8  = tid & 31;
    int r0  = (tid >> 5) * 8;
    int row0 = blockIdx.x * 64;

    unsigned long long acc[8][4];
    #pragma unroll
    for (int r = 0; r < 8; r++)
        #pragma unroll
        for (int j = 0; j < 4; j++) acc[r][j] = 0ull;

    for (int k0 = 0; k0 < HID; k0 += 16) {
        #pragma unroll
        for (int i = 0; i < 4; i++) {
            int q = tid + i * 256;
            int kk = q >> 6, cc = q & 63;
            float4 v = *(const float4*)&W[(size_t)(k0 + kk) * 256 + cc * 4];
            if (cc & 1) Wsb[kk][cc >> 1] = v; else Wsa[kk][cc >> 1] = v;
        }
        {
            int q = tid;
            int r = q >> 2, kq = (q & 3) * 4;
            int gr = row0 + r;
            float4 hv = make_float4(0.f, 0.f, 0.f, 0.f);
            if (gr < n) hv = *(const float4*)&H[(size_t)gr * HID + k0 + kq];
            Hs2[kq + 0][r] = make_float2(hv.x, hv.x);
            Hs2[kq + 1][r] = make_float2(hv.y, hv.y);
            Hs2[kq + 2][r] = make_float2(hv.z, hv.z);
            Hs2[kq + 3][r] = make_float2(hv.w, hv.w);
        }
        __syncthreads();
        #pragma unroll
        for (int kk = 0; kk < 16; kk++) {
            ulonglong2 wa = *(ulonglong2*)&Wsa[kk][c8];
            ulonglong2 wb = *(ulonglong2*)&Wsb[kk][c8];
            #pragma unroll
            for (int r = 0; r < 8; r++) {
                unsigned long long h2 = *(unsigned long long*)&Hs2[kk][r0 + r];
                acc[r][0] = ffma2(h2, wa.x, acc[r][0]);
                acc[r][1] = ffma2(h2, wa.y, acc[r][1]);
                acc[r][2] = ffma2(h2, wb.x, acc[r][2]);
                acc[r][3] = ffma2(h2, wb.y, acc[r][3]);
            }
        }
        __syncthreads();
    }
    float4 bv0 = *(const float4*)&bias[c8 * 8];
    float4 bv1 = *(const float4*)&bias[c8 * 8 + 4];
    #pragma unroll
    for (int r = 0; r < 8; r++) {
        int gr = row0 + r0 + r;
        if (gr < n) {
            float2 p0 = *(float2*)&acc[r][0];
            float2 p1 = *(float2*)&acc[r][1];
            float2 p2 = *(float2*)&acc[r][2];
            float2 p3 = *(float2*)&acc[r][3];
            float4 o0 = make_float4(p0.x + bv0.x, p0.y + bv0.y, p1.x + bv0.z, p1.y + bv0.w);
            float4 o1 = make_float4(p2.x + bv1.x, p2.y + bv1.y, p3.x + bv1.z, p3.y + bv1.w);
            *(float4*)&O[(size_t)gr * 256 + c8 * 8]     = o0;
            *(float4*)&O[(size_t)gr * 256 + c8 * 8 + 4] = o1;
        }
    }
}

// ---------- per-edge MLP head, grouped by dst, unroll 4 ----------
__device__ __forceinline__ float edge_dot(float4 A, float4 Bb, float4 ev,
                                          float4 w0, float4 w1, float4 w2, float4 w3,
                                          float4 v2) {
    float4 z;
    z.x = A.x + Bb.x + ev.x*w0.x + ev.y*w1.x + ev.z*w2.x + ev.w*w3.x;
    z.y = A.y + Bb.y + ev.x*w0.y + ev.y*w1.y + ev.z*w2.y + ev.w*w3.y;
    z.z = A.z + Bb.z + ev.x*w0.z + ev.y*w1.z + ev.z*w2.z + ev.w*w3.z;
    z.w = A.w + Bb.w + ev.x*w0.w + ev.y*w1.w + ev.z*w2.w + ev.w*w3.w;
    return fmaxf(z.x,0.f)*v2.x + fmaxf(z.y,0.f)*v2.y + fmaxf(z.z,0.f)*v2.z + fmaxf(z.w,0.f)*v2.w;
}

__global__ void edge_kernel(const float* __restrict__ ea,
                            const float* __restrict__ WmE,
                            const float* __restrict__ bm1, const float* __restrict__ Wm2,
                            const float* __restrict__ bm2, float* __restrict__ out, int n) {
    __shared__ float4 sWe[4][32];
    __shared__ float4 sb4[32];
    __shared__ float4 sw24[32];
    __shared__ float sbm2;
    int tid = threadIdx.x;  // 256
    if (tid < 128) sWe[tid >> 5][tid & 31] = *(const float4*)&WmE[(tid >> 5) * HID + (tid & 31) * 4];
    else if (tid < 160) sb4[tid - 128] = *(const float4*)&bm1[(tid - 128) * 4];
    else if (tid < 192) sw24[tid - 160] = *(const float4*)&Wm2[(tid - 160) * 4];
    else if (tid == 192) sbm2 = bm2[0];
    __syncthreads();
    int gwid = (blockIdx.x * blockDim.x + tid) >> 5;
    int lane = tid & 31;
    if (gwid >= n) return;
    int node = gwid;
    int beg = g_rowptr[node], end = g_rowptr[node + 1];
    if (beg == end) return;
    float4 Bb = *(const float4*)&g_ab[(size_t)node * 256 + HID + lane * 4];
    float4 bi = sb4[lane];
    Bb.x += bi.x; Bb.y += bi.y; Bb.z += bi.z; Bb.w += bi.w;
    float4 w0 = sWe[0][lane], w1 = sWe[1][lane], w2 = sWe[2][lane], w3 = sWe[3][lane];
    float4 v2 = sw24[lane];
    float bm2v = sbm2;
    int e = beg;
    for (; e + 3 < end; e += 4) {
        int2 se0 = __ldg(&g_se[e]);
        int2 se1 = __ldg(&g_se[e + 1]);
        int2 se2 = __ldg(&g_se[e + 2]);
        int2 se3 = __ldg(&g_se[e + 3]);
        float4 A0 = __ldg((const float4*)(g_ab + (size_t)se0.x * 256) + lane);
        float4 A1 = __ldg((const float4*)(g_ab + (size_t)se1.x * 256) + lane);
        float4 A2 = __ldg((const float4*)(g_ab + (size_t)se2.x * 256) + lane);
        float4 A3 = __ldg((const float4*)(g_ab + (size_t)se3.x * 256) + lane);
        float4 ev0 = __ldg((const float4*)&ea[(size_t)se0.y * 4]);
        float4 ev1 = __ldg((const float4*)&ea[(size_t)se1.y * 4]);
        float4 ev2 = __ldg((const float4*)&ea[(size_t)se2.y * 4]);
        float4 ev3 = __ldg((const float4*)&ea[(size_t)se3.y * 4]);
        float p0 = edge_dot(A0, Bb, ev0, w0, w1, w2, w3, v2);
        float p1 = edge_dot(A1, Bb, ev1, w0, w1, w2, w3, v2);
        float p2 = edge_dot(A2, Bb, ev2, w0, w1, w2, w3, v2);
        float p3 = edge_dot(A3, Bb, ev3, w0, w1, w2, w3, v2);
        #pragma unroll
        for (int off = 16; off; off >>= 1) {
            p0 += __shfl_xor_sync(0xffffffffu, p0, off);
            p1 += __shfl_xor_sync(0xffffffffu, p1, off);
            p2 += __shfl_xor_sync(0xffffffffu, p2, off);
            p3 += __shfl_xor_sync(0xffffffffu, p3, off);
        }
        if (lane == 0) out[se0.y] = 1.f / (1.f + __expf(-(p0 + bm2v)));
        if (lane == 1) out[se1.y] = 1.f / (1.f + __expf(-(p1 + bm2v)));
        if (lane == 2) out[se2.y] = 1.f / (1.f + __expf(-(p2 + bm2v)));
        if (lane == 3) out[se3.y] = 1.f / (1.f + __expf(-(p3 + bm2v)));
    }
    for (; e < end; e++) {
        int2 se0 = __ldg(&g_se[e]);
        float4 A0 = __ldg((const float4*)(g_ab + (size_t)se0.x * 256) + lane);
        float4 ev0 = __ldg((const float4*)&ea[(size_t)se0.y * 4]);
        float p0 = edge_dot(A0, Bb, ev0, w0, w1, w2, w3, v2);
        #pragma unroll
        for (int off = 16; off; off >>= 1)
            p0 += __shfl_xor_sync(0xffffffffu, p0, off);
        if (lane == 0) out[se0.y] = 1.f / (1.f + __expf(-(p0 + bm2v)));
    }
}

// ---------- launcher ----------
extern "C" void kernel_launch(void* const* d_in, const int* in_sizes, int n_in,
                              void* d_out, int out_size) {
    const float* x    = (const float*)d_in[0];
    const float* ea   = (const float*)d_in[1];
    const float* W1   = (const float*)d_in[2];
    const float* b1   = (const float*)d_in[3];
    const float* W2   = (const float*)d_in[4];
    const float* b2   = (const float*)d_in[5];
    const float* Wm1  = (const float*)d_in[6];
    const float* bm1  = (const float*)d_in[7];
    const float* Wm2  = (const float*)d_in[8];
    const float* bm2  = (const float*)d_in[9];
    const int*   ei   = (const int*)d_in[10];   // int32 (JAX x64 disabled)
    float* out = (float*)d_out;

    int n = in_sizes[0] / 5;          // 50000
    int E = in_sizes[10] / 2;         // 800000
    int nb = (n + 255) / 256;

    float *p_t, *p_ab, *p_w2ab, *p_bab;
    cudaGetSymbolAddress((void**)&p_t, g_t);
    cudaGetSymbolAddress((void**)&p_ab, g_ab);
    cudaGetSymbolAddress((void**)&p_w2ab, g_w2ab);
    cudaGetSymbolAddress((void**)&p_bab, g_bab);

    // graph build — no memsets: g_deg/g_cur zeroed by prior invocation (or load)
    indeg_kernel<<<(E / 4 + 255) / 256, 256>>>(ei, E);
    disbsum_kernel<<<nb, 256>>>(n);
    rowptr2_kernel<<<nb, 256>>>(nb, n);                      // re-zeroes g_deg
    fill_kernel<<<(E + 255) / 256, 256>>>(ei, E);

    // layer 1 fused: h1 = relu(agg(x) @ W1 + b1)  (re-zeroes g_cur)
    aggx_gemm1_kernel<<<(n * 32 + 255) / 256, 256>>>(x, W1, b1, n);

    // layer 2 aggregation
    agg2_kernel<<<(n * 32 + 255) / 256, 256>>>(n);

    // combined weights + projection GEMM
    wcomb_kernel<<<129, 256>>>(W2, b2, Wm1);
    gemm256_kernel<<<(n + 63) / 64, 256>>>(p_t, p_w2ab, p_bab, p_ab, n);

    // per-edge head grouped by dst
    edge_kernel<<<(n * 32 + 255) / 256, 256>>>(ea, Wm1 + 256 * HID, bm1, Wm2, bm2, out, n);
}